// round 1
// baseline (speedup 1.0000x reference)
#include <cuda_runtime.h>
#include <cuda_bf16.h>

#define BB   4096
#define SS   128
#define DIN  64
#define DOUT 128
#define HH   32

// Precomputed fused first layer: Wc = W_net @ W1  (64 x 32), bc = b_net @ W1 + b1
__device__ float g_Wc[DIN * HH];
__device__ float g_bc[HH];

// ---------------------------------------------------------------------------
// Prologue: fold W_net (64x128) @ W1 (128x32) -> Wc (64x32); bc (32).
// grid 16 x 128 threads = 2048 threads, one Wc element each.
// ---------------------------------------------------------------------------
__global__ void prep_kernel(const float* __restrict__ Wnet,
                            const float* __restrict__ bnet,
                            const float* __restrict__ W1,
                            const float* __restrict__ b1) {
    int idx = blockIdx.x * blockDim.x + threadIdx.x;
    if (idx < DIN * HH) {
        int d = idx >> 5;      // 0..63
        int j = idx & 31;      // 0..31
        float acc = 0.f;
        #pragma unroll 8
        for (int k = 0; k < DOUT; k++)
            acc = fmaf(Wnet[d * DOUT + k], W1[k * HH + j], acc);
        g_Wc[d * HH + j] = acc;
    }
    if (idx < HH) {
        float acc = b1[idx];
        #pragma unroll 8
        for (int k = 0; k < DOUT; k++)
            acc = fmaf(bnet[k], W1[k * HH + idx], acc);
        g_bc[idx] = acc;
    }
}

// ---------------------------------------------------------------------------
// Main kernel: one batch per loop iteration, 128 threads per block.
//  - 4 warps ballot the 128-entry mask row
//  - gather the 2 selected x rows (64 floats each)
//  - h = relu(x @ Wc + bc)       (threads 0..63: r = t>>5, j = t&31)
//  - preds = h @ W2 + b2         (threads 0..7:  r = t>>2, o = t&3)
// ---------------------------------------------------------------------------
__global__ __launch_bounds__(128) void fused_kernel(
        const float*    __restrict__ x,      // [B, S, DIN]
        const unsigned* __restrict__ mask,   // [B, S] (f32 or i32 bits; !=0 test)
        const float*    __restrict__ W2,     // [HH, 4]
        const float*    __restrict__ b2,     // [4]
        float*          __restrict__ out)    // [B, 2, 4]
{
    __shared__ __align__(16) float sWc[DIN * HH];
    __shared__ float sbc[HH];
    __shared__ float sW2[HH * 4];
    __shared__ float sb2[4];
    __shared__ __align__(16) float sx[2][DIN];
    __shared__ float sh[2][HH];
    __shared__ unsigned sball[4];
    __shared__ int sinfo[3];   // i0, i1, nv

    const int tid = threadIdx.x;

    // Load per-block constants once (reused across the batch loop)
    #pragma unroll
    for (int i = tid; i < DIN * HH; i += 128) sWc[i] = g_Wc[i];
    if (tid < HH)      sbc[tid] = g_bc[tid];
    if (tid < HH * 4)  sW2[tid] = W2[tid];
    if (tid < 4)       sb2[tid] = b2[tid];
    __syncthreads();

    for (int b = blockIdx.x; b < BB; b += gridDim.x) {
        // ---- mask scan: first two valid positions + count ----
        unsigned mv  = mask[(size_t)b * SS + tid];
        unsigned bal = __ballot_sync(0xffffffffu, mv != 0u);
        if ((tid & 31) == 0) sball[tid >> 5] = bal;
        __syncthreads();

        if (tid == 0) {
            int nv = 0, i0 = -1, i1 = -1;
            #pragma unroll
            for (int w = 0; w < 4; w++) {
                unsigned bl = sball[w];
                nv += __popc(bl);
                while (bl && i1 < 0) {
                    int pos = w * 32 + (__ffs(bl) - 1);
                    if (i0 < 0) i0 = pos; else i1 = pos;
                    bl &= bl - 1;
                }
            }
            if (i0 < 0) i0 = 0;   // nv == 0: value unused, output forced to 0
            if (i1 < 0) i1 = i0;  // nv == 1: top2 uses preds[:,0] -> duplicate row
            sinfo[0] = i0; sinfo[1] = i1; sinfo[2] = nv;
        }
        __syncthreads();

        const int i0 = sinfo[0], i1 = sinfo[1], nv = sinfo[2];

        // ---- gather 2 x rows ----
        if (tid < DIN) {
            sx[0][tid] = x[((size_t)b * SS + i0) * DIN + tid];
        } else {
            int d = tid - DIN;
            sx[1][d] = x[((size_t)b * SS + i1) * DIN + d];
        }
        __syncthreads();

        // ---- h = relu(x @ Wc + bc) ----
        if (tid < 64) {
            const int r = tid >> 5;
            const int j = tid & 31;
            float acc = sbc[j];
            #pragma unroll
            for (int d = 0; d < DIN; d += 4) {
                float4 xv = *reinterpret_cast<const float4*>(&sx[r][d]);
                acc = fmaf(xv.x, sWc[(d + 0) * HH + j], acc);
                acc = fmaf(xv.y, sWc[(d + 1) * HH + j], acc);
                acc = fmaf(xv.z, sWc[(d + 2) * HH + j], acc);
                acc = fmaf(xv.w, sWc[(d + 3) * HH + j], acc);
            }
            sh[r][j] = fmaxf(acc, 0.f);
        }
        __syncthreads();

        // ---- preds = h @ W2 + b2, gated by nv ----
        if (tid < 8) {
            const int r = tid >> 2;
            const int o = tid & 3;
            float acc = sb2[o];
            #pragma unroll
            for (int k = 0; k < HH; k++)
                acc = fmaf(sh[r][k], sW2[k * 4 + o], acc);
            out[(size_t)b * 8 + r * 4 + o] = (nv >= 1) ? acc : 0.f;
        }
        __syncthreads();   // protect smem reuse across the batch loop
    }
}

// ---------------------------------------------------------------------------
// Inputs (metadata order): x, W_net, b_net, W1, b1, W2, b2, mask
// Output: float32 [4096, 2, 4]
// ---------------------------------------------------------------------------
extern "C" void kernel_launch(void* const* d_in, const int* in_sizes, int n_in,
                              void* d_out, int out_size) {
    const float*    x    = (const float*)d_in[0];
    const float*    Wnet = (const float*)d_in[1];
    const float*    bnet = (const float*)d_in[2];
    const float*    W1   = (const float*)d_in[3];
    const float*    b1   = (const float*)d_in[4];
    const float*    W2   = (const float*)d_in[5];
    const float*    b2   = (const float*)d_in[6];
    const unsigned* mask = (const unsigned*)d_in[7];
    float* out = (float*)d_out;

    prep_kernel<<<16, 128>>>(Wnet, bnet, W1, b1);
    fused_kernel<<<2048, 128>>>(x, mask, W2, b2, out);
}

// round 2
// speedup vs baseline: 1.2987x; 1.2987x over previous
#include <cuda_runtime.h>
#include <cuda_bf16.h>

#define BB   4096
#define SS   128
#define DIN  64
#define DOUT 128
#define HH   32

// Precomputed fused first layer: Wc = W_net @ W1  (64 x 32), bc = b_net @ W1 + b1
__device__ float g_Wc[DIN * HH];
__device__ float g_bc[HH];

// ---------------------------------------------------------------------------
// Prologue: fold W_net (64x128) @ W1 (128x32) -> Wc (64x32); bc (32).
// 16 blocks x 128 threads = 2048 threads, one Wc element each. Full unroll
// so ptxas front-batches the loads (high MLP).
// ---------------------------------------------------------------------------
__global__ void prep_kernel(const float* __restrict__ Wnet,
                            const float* __restrict__ bnet,
                            const float* __restrict__ W1,
                            const float* __restrict__ b1) {
    int idx = blockIdx.x * blockDim.x + threadIdx.x;
    if (idx < DIN * HH) {
        int d = idx >> 5;      // 0..63  (uniform per warp)
        int j = idx & 31;      // 0..31  (lane)
        float acc = 0.f;
        #pragma unroll
        for (int k = 0; k < DOUT; k++)
            acc = fmaf(__ldg(&Wnet[d * DOUT + k]), __ldg(&W1[k * HH + j]), acc);
        g_Wc[d * HH + j] = acc;
    }
    if (idx < HH) {
        float acc = b1[idx];
        #pragma unroll
        for (int k = 0; k < DOUT; k++)
            acc = fmaf(bnet[k], W1[k * HH + idx], acc);
        g_bc[idx] = acc;
    }
}

// ---------------------------------------------------------------------------
// Main kernel: warp-per-batch, no block-wide syncs.
//   grid = 512 blocks x 256 threads (8 warps) -> 4096 warps = 4096 batches.
// ---------------------------------------------------------------------------
__global__ __launch_bounds__(256) void fused_kernel(
        const float*    __restrict__ x,      // [B, S, DIN]
        const unsigned* __restrict__ mask,   // [B, S] (f32 or i32 bits; !=0)
        const float*    __restrict__ W2,     // [HH, 4]
        const float*    __restrict__ b2,     // [4]
        float*          __restrict__ out)    // [B, 2, 4]
{
    __shared__ __align__(16) float sx[8][2][DIN];   // per-warp x slabs, 4 KB

    const int warp = threadIdx.x >> 5;
    const int lane = threadIdx.x & 31;
    const int b    = blockIdx.x * 8 + warp;

    // ---- per-lane weights (issued early; L1-hot after first warp/SM) ----
    float wc[DIN];                       // Wc column `lane`
    #pragma unroll
    for (int d = 0; d < DIN; d++) wc[d] = g_Wc[d * HH + lane];
    const float  bcj = g_bc[lane];
    const float4 w2v = *reinterpret_cast<const float4*>(W2 + lane * 4); // W2 row `lane`
    const float4 b2v = *reinterpret_cast<const float4*>(b2);

    // ---- mask scan: 128 entries via uint4/lane, warp-uniform result ----
    const uint4 mv = *reinterpret_cast<const uint4*>(mask + (size_t)b * SS + lane * 4);
    unsigned bits = (mv.x != 0u ? 1u : 0u) | (mv.y != 0u ? 2u : 0u)
                  | (mv.z != 0u ? 4u : 0u) | (mv.w != 0u ? 8u : 0u);
    const unsigned any = __ballot_sync(0xffffffffu, bits != 0u);

    int i0 = 0, i1 = 0;
    const bool valid = (any != 0u);
    if (valid) {
        const int t0 = __ffs(any) - 1;
        const unsigned b0 = __shfl_sync(0xffffffffu, bits, t0);
        i0 = t0 * 4 + (__ffs(b0) - 1);
        const unsigned b0r = b0 & (b0 - 1);
        if (b0r) {
            i1 = t0 * 4 + (__ffs(b0r) - 1);          // second hit in same lane
        } else {
            const unsigned any2 = any & (any - 1);
            if (any2) {
                const int t1 = __ffs(any2) - 1;
                const unsigned b1b = __shfl_sync(0xffffffffu, bits, t1);
                i1 = t1 * 4 + (__ffs(b1b) - 1);
            } else {
                i1 = i0;                              // nv==1: top2 = preds[:,0]
            }
        }
    }

    // ---- gather the two x rows (half-warp each, float4) ----
    {
        const int r   = lane >> 4;                    // 0..1
        const int c   = (lane & 15) * 4;              // 0..60
        const int row = r ? i1 : i0;
        const float4 xv = *reinterpret_cast<const float4*>(
            x + ((size_t)b * SS + row) * DIN + c);
        *reinterpret_cast<float4*>(&sx[warp][r][c]) = xv;
    }
    __syncwarp();

    // ---- h = relu(x @ Wc + bc): 1 LDS-broadcast + 1 FMA per step ----
    float h0 = bcj, h1 = bcj;
    #pragma unroll
    for (int d = 0; d < DIN; d++) {
        h0 = fmaf(sx[warp][0][d], wc[d], h0);
        h1 = fmaf(sx[warp][1][d], wc[d], h1);
    }
    h0 = fmaxf(h0, 0.f);
    h1 = fmaxf(h1, 0.f);

    // ---- preds = h @ W2 (+ b2): 8 warp butterfly reductions ----
    float p[8];
    p[0] = h0 * w2v.x;  p[1] = h0 * w2v.y;  p[2] = h0 * w2v.z;  p[3] = h0 * w2v.w;
    p[4] = h1 * w2v.x;  p[5] = h1 * w2v.y;  p[6] = h1 * w2v.z;  p[7] = h1 * w2v.w;
    #pragma unroll
    for (int i = 0; i < 8; i++) {
        #pragma unroll
        for (int off = 16; off; off >>= 1)
            p[i] += __shfl_xor_sync(0xffffffffu, p[i], off);
    }

    if (lane == 0) {
        float4 o0, o1;
        if (valid) {
            o0 = make_float4(p[0] + b2v.x, p[1] + b2v.y, p[2] + b2v.z, p[3] + b2v.w);
            o1 = make_float4(p[4] + b2v.x, p[5] + b2v.y, p[6] + b2v.z, p[7] + b2v.w);
        } else {
            o0 = make_float4(0.f, 0.f, 0.f, 0.f);
            o1 = o0;
        }
        float4* ob = reinterpret_cast<float4*>(out + (size_t)b * 8);
        ob[0] = o0;
        ob[1] = o1;
    }
}

// ---------------------------------------------------------------------------
// Inputs (metadata order): x, W_net, b_net, W1, b1, W2, b2, mask
// Output: float32 [4096, 2, 4]
// ---------------------------------------------------------------------------
extern "C" void kernel_launch(void* const* d_in, const int* in_sizes, int n_in,
                              void* d_out, int out_size) {
    const float*    x    = (const float*)d_in[0];
    const float*    Wnet = (const float*)d_in[1];
    const float*    bnet = (const float*)d_in[2];
    const float*    W1   = (const float*)d_in[3];
    const float*    b1   = (const float*)d_in[4];
    const float*    W2   = (const float*)d_in[5];
    const float*    b2   = (const float*)d_in[6];
    const unsigned* mask = (const unsigned*)d_in[7];
    float* out = (float*)d_out;

    prep_kernel<<<16, 128>>>(Wnet, bnet, W1, b1);
    fused_kernel<<<512, 256>>>(x, mask, W2, b2, out);
}

// round 3
// speedup vs baseline: 1.4742x; 1.1351x over previous
#include <cuda_runtime.h>
#include <cuda_bf16.h>

#define BB   4096
#define SS   128
#define DIN  64
#define DOUT 128
#define HH   32
#define WCT_PITCH 68   // 64 + 4 pad: per-lane LDS.128 conflict-free

// Transposed fused first layer: WcT[j][d] = (W_net @ W1)[d][j]; bc = b_net@W1 + b1
__device__ float g_WcT[HH * DIN];
__device__ float g_bc[HH];

// ---------------------------------------------------------------------------
// Prologue: warp-per-element fold. we < 2048: Wc element (d = we>>5, j = we&31),
// 32-way K split + butterfly reduce. we in [2048, 2080): bc element.
// ---------------------------------------------------------------------------
__global__ __launch_bounds__(256) void prep_kernel(
        const float* __restrict__ Wnet, const float* __restrict__ bnet,
        const float* __restrict__ W1,   const float* __restrict__ b1) {
    const int warp = threadIdx.x >> 5;
    const int lane = threadIdx.x & 31;
    const int we   = blockIdx.x * 8 + warp;

    if (we < DIN * HH) {
        const int d = we >> 5, j = we & 31;
        const float4 wn = *reinterpret_cast<const float4*>(Wnet + d * DOUT + lane * 4);
        const int k = lane * 4;
        float acc = wn.x * W1[(k + 0) * HH + j];
        acc = fmaf(wn.y, W1[(k + 1) * HH + j], acc);
        acc = fmaf(wn.z, W1[(k + 2) * HH + j], acc);
        acc = fmaf(wn.w, W1[(k + 3) * HH + j], acc);
        #pragma unroll
        for (int off = 16; off; off >>= 1)
            acc += __shfl_xor_sync(0xffffffffu, acc, off);
        if (lane == 0) g_WcT[j * DIN + d] = acc;
    } else if (we < DIN * HH + HH) {
        const int j = we - DIN * HH;
        const int k = lane * 4;
        float acc = bnet[k + 0] * W1[(k + 0) * HH + j];
        acc = fmaf(bnet[k + 1], W1[(k + 1) * HH + j], acc);
        acc = fmaf(bnet[k + 2], W1[(k + 2) * HH + j], acc);
        acc = fmaf(bnet[k + 3], W1[(k + 3) * HH + j], acc);
        #pragma unroll
        for (int off = 16; off; off >>= 1)
            acc += __shfl_xor_sync(0xffffffffu, acc, off);
        if (lane == 0) g_bc[j] = b1[j] + acc;
    }
}

// ---------------------------------------------------------------------------
// Main kernel: warp-per-batch. Mask load and speculative x-row loads (rows
// 0..3) issued concurrently; ~97% of batches resolve from the prefetch.
// ---------------------------------------------------------------------------
__global__ __launch_bounds__(256) void fused_kernel(
        const float*    __restrict__ x,      // [B, S, DIN]
        const unsigned* __restrict__ mask,   // [B, S] (f32/i32 bits; !=0)
        const float*    __restrict__ W2,     // [HH, 4]
        const float*    __restrict__ b2,     // [4]
        float*          __restrict__ out)    // [B, 2, 4]
{
    __shared__ __align__(16) float sWcT[HH * WCT_PITCH];       // 8.5 KB
    __shared__ __align__(16) float sxx[8][6][DIN];             // 6 KB: 4 spec + 2 fallback

    const int warp = threadIdx.x >> 5;
    const int lane = threadIdx.x & 31;
    const int b    = blockIdx.x * 8 + warp;
    const float* xb = x + (size_t)b * SS * DIN;

    // ---- issue ALL long-latency loads up front (independent) ----
    const uint4 mv = *reinterpret_cast<const uint4*>(mask + (size_t)b * SS + lane * 4);
    const int pr = lane >> 4;                 // 0/1: this half-warp's rows
    const int pc = (lane & 15) * 4;
    const float4 xa = *reinterpret_cast<const float4*>(xb + (pr + 0) * DIN + pc);
    const float4 xc = *reinterpret_cast<const float4*>(xb + (pr + 2) * DIN + pc);
    const float  bcj = g_bc[lane];
    const float4 w2v = *reinterpret_cast<const float4*>(W2 + lane * 4);
    const float4 b2v = *reinterpret_cast<const float4*>(b2);

    // ---- stage block-shared WcT (once) ----
    #pragma unroll
    for (int i = threadIdx.x; i < HH * DIN; i += 256) {
        const int j = i >> 6, d = i & 63;
        sWcT[j * WCT_PITCH + d] = g_WcT[i];
    }

    // ---- stage speculative rows 0..3 ----
    *reinterpret_cast<float4*>(&sxx[warp][pr + 0][pc]) = xa;
    *reinterpret_cast<float4*>(&sxx[warp][pr + 2][pc]) = xc;

    // ---- mask scan: first two valid positions ----
    unsigned bits = (mv.x != 0u ? 1u : 0u) | (mv.y != 0u ? 2u : 0u)
                  | (mv.z != 0u ? 4u : 0u) | (mv.w != 0u ? 8u : 0u);
    const unsigned any = __ballot_sync(0xffffffffu, bits != 0u);
    const bool valid = (any != 0u);
    int i0 = 0, i1 = 0;
    if (valid) {
        const int t0 = __ffs(any) - 1;
        const unsigned c0 = __shfl_sync(0xffffffffu, bits, t0);
        i0 = t0 * 4 + (__ffs(c0) - 1);
        const unsigned c0r = c0 & (c0 - 1);
        if (c0r) {
            i1 = t0 * 4 + (__ffs(c0r) - 1);
        } else {
            const unsigned any2 = any & (any - 1);
            if (any2) {
                const int t1 = __ffs(any2) - 1;
                const unsigned c1 = __shfl_sync(0xffffffffu, bits, t1);
                i1 = t1 * 4 + (__ffs(c1) - 1);
            } else {
                i1 = i0;          // nv==1: top2 = preds[:,0]
            }
        }
    }

    // ---- rare fallback: needed row not in the speculative set ----
    int s0 = i0, s1 = i1;
    if (i0 >= 4) {                 // warp-uniform branch
        if (lane < 16)
            *reinterpret_cast<float4*>(&sxx[warp][4][(lane & 15) * 4]) =
                *reinterpret_cast<const float4*>(xb + i0 * DIN + (lane & 15) * 4);
        s0 = 4;
    }
    if (i1 >= 4) {
        if (lane >= 16)
            *reinterpret_cast<float4*>(&sxx[warp][5][(lane & 15) * 4]) =
                *reinterpret_cast<const float4*>(xb + i1 * DIN + (lane & 15) * 4);
        s1 = (i1 == i0) ? 4 : 5;
    }

    __syncthreads();               // WcT staged + this warp's rows visible

    // ---- h = relu(x @ Wc + bc): LDS.128-based, conflict-free ----
    const float* xr0 = sxx[warp][s0];
    const float* xr1 = sxx[warp][s1];
    const float* wrow = sWcT + lane * WCT_PITCH;
    float h0 = bcj, h1 = bcj;
    #pragma unroll
    for (int d = 0; d < DIN; d += 4) {
        const float4 wv = *reinterpret_cast<const float4*>(wrow + d);
        const float4 x0 = *reinterpret_cast<const float4*>(xr0 + d);
        const float4 x1 = *reinterpret_cast<const float4*>(xr1 + d);
        h0 = fmaf(x0.x, wv.x, h0); h1 = fmaf(x1.x, wv.x, h1);
        h0 = fmaf(x0.y, wv.y, h0); h1 = fmaf(x1.y, wv.y, h1);
        h0 = fmaf(x0.z, wv.z, h0); h1 = fmaf(x1.z, wv.z, h1);
        h0 = fmaf(x0.w, wv.w, h0); h1 = fmaf(x1.w, wv.w, h1);
    }
    h0 = fmaxf(h0, 0.f);
    h1 = fmaxf(h1, 0.f);

    // ---- preds = h @ W2 (+ b2): 8 warp butterfly reductions ----
    float p[8];
    p[0] = h0 * w2v.x;  p[1] = h0 * w2v.y;  p[2] = h0 * w2v.z;  p[3] = h0 * w2v.w;
    p[4] = h1 * w2v.x;  p[5] = h1 * w2v.y;  p[6] = h1 * w2v.z;  p[7] = h1 * w2v.w;
    #pragma unroll
    for (int i = 0; i < 8; i++) {
        #pragma unroll
        for (int off = 16; off; off >>= 1)
            p[i] += __shfl_xor_sync(0xffffffffu, p[i], off);
    }

    if (lane == 0) {
        float4 o0, o1;
        if (valid) {
            o0 = make_float4(p[0] + b2v.x, p[1] + b2v.y, p[2] + b2v.z, p[3] + b2v.w);
            o1 = make_float4(p[4] + b2v.x, p[5] + b2v.y, p[6] + b2v.z, p[7] + b2v.w);
        } else {
            o0 = make_float4(0.f, 0.f, 0.f, 0.f);
            o1 = o0;
        }
        float4* ob = reinterpret_cast<float4*>(out + (size_t)b * 8);
        ob[0] = o0;
        ob[1] = o1;
    }
}

// ---------------------------------------------------------------------------
// Inputs (metadata order): x, W_net, b_net, W1, b1, W2, b2, mask
// Output: float32 [4096, 2, 4]
// ---------------------------------------------------------------------------
extern "C" void kernel_launch(void* const* d_in, const int* in_sizes, int n_in,
                              void* d_out, int out_size) {
    const float*    x    = (const float*)d_in[0];
    const float*    Wnet = (const float*)d_in[1];
    const float*    bnet = (const float*)d_in[2];
    const float*    W1   = (const float*)d_in[3];
    const float*    b1   = (const float*)d_in[4];
    const float*    W2   = (const float*)d_in[5];
    const float*    b2   = (const float*)d_in[6];
    const unsigned* mask = (const unsigned*)d_in[7];
    float* out = (float*)d_out;

    prep_kernel<<<260, 256>>>(Wnet, bnet, W1, b1);
    fused_kernel<<<512, 256>>>(x, mask, W2, b2, out);
}